// round 13
// baseline (speedup 1.0000x reference)
#include <cuda_runtime.h>
#include <cuda_bf16.h>
#include <cstdint>

// FirstSpikeDetector: out[b][t] = 1 iff spike_train[b][t] is the first nonzero
// in row b, else 0. Input values are exact 0.0f / 1.0f.
//
// R13: split-fill. R7-R12 established:
//   - memset fill path: ~6.2 TB/s, optimal zero-writer.
//   - any small second kernel node costs ~5-6.5us nearly INDEPENDENT of its
//     work (R8 no-op fixup 4.8us; R12 halving reads moved the bench 0.03us).
// => the detector's ~6.5us is a fixed window with idle store capacity.
// So: memset covers rows [0, rows-4096) = 96MB (~15.5us); the detector
// fills the last 4096 rows (32MB) itself R1-style (16x STG.128/lane with
// one-hot injection) -- ~6us of SM store streaming hidden inside the node
// floor -- while doing detection for ALL rows as before.
//
// Falsified (do not retry): .cs hints (R2), store-burst-before-ballot (R2/R3),
// persistent grids (R3), rows/warp batching (R4/R9), STG.256 (R6), 2D pitched
// memset (R8), fork/join overlap with memset nodes (R8/R10), shrinking
// detector reads (R12 -- node time is work-insensitive).

static constexpr int T    = 2048;    // time steps per row
static constexpr int TV4  = T / 4;   // float4s per row (512)
static constexpr int FILL_ROWS = 4096;   // rows the detector fills itself (32MB)

__global__ void __launch_bounds__(256)
first_spike_detect(const float* __restrict__ in, float* __restrict__ out,
                   int rows, int ms_rows /* rows covered by the memset */)
{
    const int gtid = blockIdx.x * blockDim.x + threadIdx.x;
    const int warp = gtid >> 5;               // one warp = one row
    const int lane = gtid & 31;
    if (warp >= rows) return;

    const float4* __restrict__ row_in =
        reinterpret_cast<const float4*>(in) + (size_t)warp * TV4;
    float* __restrict__ row_out = out + (size_t)warp * T;
    float4* __restrict__ row_out4 = reinterpret_cast<float4*>(row_out);

    // ---- scan elements 0..127 (1 x LDG.128 per lane) ----
    const float4 v = row_in[lane];
    const unsigned q = (v.x != 0.0f ? 1u : 0u) | (v.y != 0.0f ? 2u : 0u) |
                       (v.z != 0.0f ? 4u : 0u) | (v.w != 0.0f ? 8u : 0u);
    const unsigned m = __ballot_sync(0xffffffffu, q != 0u);

    if (warp < ms_rows) {
        // ===== memset-covered row: cheap path (R7) =====
        if (m != 0u) {
            const int src = __ffs(m) - 1;
            if (lane == src) {
                row_out[(src << 2) + (__ffs(q) - 1)] = 1.0f;
            }
            return;
        }
        // Rare path (P ~ 1.4e-6): keep scanning in 128-chunks.
        #pragma unroll 1
        for (int base = 128; base < T; base += 128) {
            const float4 u = row_in[(base >> 2) + lane];
            const unsigned q2 = (u.x != 0.0f ? 1u : 0u) | (u.y != 0.0f ? 2u : 0u) |
                                (u.z != 0.0f ? 4u : 0u) | (u.w != 0.0f ? 8u : 0u);
            const unsigned m2 = __ballot_sync(0xffffffffu, q2 != 0u);
            if (m2) {
                const int s2 = __ffs(m2) - 1;
                if (lane == s2) {
                    row_out[base + (s2 << 2) + (__ffs(q2) - 1)] = 1.0f;
                }
                return;
            }
        }
        return;   // no spike: memset zeros are correct
    }

    // ===== detector-filled row: fused path (R1) =====
    int f = -1;   // warp-uniform first-spike index (within window) or -1
    if (m != 0u) {
        const int src = __ffs(m) - 1;
        int sub = __ffs(q) - 1;                      // valid on lane src
        sub = __shfl_sync(0xffffffffu, sub, src);
        f = (src << 2) + sub;
    }

    // Fill the whole row: 16 x STG.128 per lane, one-hot injected.
    const int lbase = lane << 2;
    #pragma unroll
    for (int i = 0; i < 16; i++) {
        const int base = i * 128 + lbase;            // float index of slot 0
        float4 w;
        w.x = (base + 0 == f) ? 1.0f : 0.0f;
        w.y = (base + 1 == f) ? 1.0f : 0.0f;
        w.z = (base + 2 == f) ? 1.0f : 0.0f;
        w.w = (base + 3 == f) ? 1.0f : 0.0f;
        row_out4[i * 32 + lane] = w;
    }

    if (m == 0u) {
        // Rare path: zeros already stored above; find the spike and overwrite.
        int first = -1;
        #pragma unroll 1
        for (int base = 128; base < T; base += 128) {
            const float4 u = row_in[(base >> 2) + lane];
            const unsigned q2 = (u.x != 0.0f ? 1u : 0u) | (u.y != 0.0f ? 2u : 0u) |
                                (u.z != 0.0f ? 4u : 0u) | (u.w != 0.0f ? 8u : 0u);
            const unsigned m2 = __ballot_sync(0xffffffffu, q2 != 0u);
            if (m2) {
                const int s2 = __ffs(m2) - 1;
                if (lane == s2) {
                    first = base + (s2 << 2) + (__ffs(q2) - 1);
                }
                break;   // warp-uniform exit
            }
        }
        __syncwarp();    // order cross-lane zero stores before the overwrite
        if (first >= 0) {
            row_out[first] = 1.0f;
        }
    }
}

extern "C" void kernel_launch(void* const* d_in, const int* in_sizes, int n_in,
                              void* d_out, int out_size)
{
    const float* in = (const float*)d_in[0];
    float* out = (float*)d_out;
    const int rows = in_sizes[0] / T;                  // 16384

    const int fill_rows = (rows < FILL_ROWS) ? rows : FILL_ROWS;
    const int ms_rows   = rows - fill_rows;            // 12288

    // Node 1: memset zeros rows [0, ms_rows) -- 96MB contiguous.
    if (ms_rows > 0) {
        cudaMemsetAsync(d_out, 0, (size_t)ms_rows * T * sizeof(float), 0);
    }

    // Node 2: detector for all rows; fills the last fill_rows rows itself.
    const int threads = 256;                                   // 8 warps/block
    const int blocks  = (rows * 32 + threads - 1) / threads;   // 2048
    first_spike_detect<<<blocks, threads>>>(in, out, rows, ms_rows);
}

// round 14
// speedup vs baseline: 1.1633x; 1.1633x over previous
#include <cuda_runtime.h>
#include <cuda_bf16.h>
#include <cstdint>

// FirstSpikeDetector: out[b][t] = 1 iff spike_train[b][t] is the first nonzero
// in row b, else 0. Input values are exact 0.0f / 1.0f.
//
// R14: fused single-node kernel at minimum DRAM bytes.
// 13 rounds established: bench ~= total DRAM bytes / ~5.0 TB/s (steady-state
// HBM write wall), nearly structure-independent. Output 128MB is compulsory;
// the only knob left is read bytes + node count.
//   - ONE kernel (no memset node, no node boundary), R1's exact store
//     structure (the best-measured SM fill: 16x STG.128/lane with the
//     compare-in-loop one-hot -- R5/R6 alternates all lost to it).
//   - scan window shrunk to 64 elements: one LDG.64 (float2) per lane,
//     256B/row = 4MB total read. P(no spike in window) = 0.9^64 ~ 1.2e-3
//     -> ~20 of 16384 rows re-scan from 0 in 128-chunks (negligible).
// Total bytes 132MB in one node -> predicted ~26.5us.
//
// Falsified (do not retry): .cs/.ldcs (R2), store-before-ballot bursts (R2/R3),
// persistent grids (R3), multi-row fused batching (R4), branch-free store
// loop (R5), STG.256 (R6), 2D pitched memset (R8), fork/join overlap with
// memset nodes (R8/R10), shrinking a SEPARATE detector's reads (R12, node
// time work-insensitive), split-fill into the detector node (R13).

static constexpr int T   = 2048;    // time steps per row
static constexpr int TV4 = T / 4;   // float4s per row (512)

__global__ void __launch_bounds__(256)
first_spike_fused(const float* __restrict__ in, float* __restrict__ out, int rows)
{
    const int gtid = blockIdx.x * blockDim.x + threadIdx.x;
    const int warp = gtid >> 5;               // one warp = one row
    const int lane = gtid & 31;
    if (warp >= rows) return;

    const float* __restrict__ row_in = in + (size_t)warp * T;
    const float2* __restrict__ row_in2 = reinterpret_cast<const float2*>(row_in);
    const float4* __restrict__ row_in4 = reinterpret_cast<const float4*>(row_in);
    float4* __restrict__ row_out4 =
        reinterpret_cast<float4*>(out) + (size_t)warp * TV4;

    // ---- scan window: elements 0..63, one LDG.64 per lane ----
    const float2 v = row_in2[lane];
    const unsigned q = (v.x != 0.0f ? 1u : 0u) | (v.y != 0.0f ? 2u : 0u);
    const unsigned m = __ballot_sync(0xffffffffu, q != 0u);

    int first = T;   // warp-uniform first-spike index; T = no spike
    if (m != 0u) {
        const int src = __ffs(m) - 1;
        int sub = __ffs(q) - 1;                       // valid on lane src
        sub = __shfl_sync(0xffffffffu, sub, src);
        first = (src << 1) + sub;
    } else {
        // Rare path (P ~ 1.2e-3 per row): rescan from 0 in 128-elem chunks
        // (re-reading the 64-elem window costs nothing at this frequency).
        #pragma unroll 1
        for (int base = 0; base < T; base += 128) {
            const float4 u = row_in4[(base >> 2) + lane];
            const unsigned q2 = (u.x != 0.0f ? 1u : 0u) | (u.y != 0.0f ? 2u : 0u) |
                                (u.z != 0.0f ? 4u : 0u) | (u.w != 0.0f ? 8u : 0u);
            const unsigned m2 = __ballot_sync(0xffffffffu, q2 != 0u);
            if (m2) {
                const int s2 = __ffs(m2) - 1;
                int sub2 = __ffs(q2) - 1;             // valid on lane s2
                sub2 = __shfl_sync(0xffffffffu, sub2, s2);
                first = base + (s2 << 2) + sub2;
                break;                                // warp-uniform exit
            }
        }
    }

    // ---- store pass: R1's exact structure (best-measured SM fill) ----
    const int fq = first >> 2;    // which float4 holds the spike (512 if none)
    const int fr = first & 3;

    #pragma unroll
    for (int i = lane; i < TV4; i += 32) {
        float4 z = make_float4(0.0f, 0.0f, 0.0f, 0.0f);
        if (i == fq) {
            if      (fr == 0) z.x = 1.0f;
            else if (fr == 1) z.y = 1.0f;
            else if (fr == 2) z.z = 1.0f;
            else              z.w = 1.0f;
        }
        row_out4[i] = z;
    }
}

extern "C" void kernel_launch(void* const* d_in, const int* in_sizes, int n_in,
                              void* d_out, int out_size)
{
    const float* in = (const float*)d_in[0];
    float* out = (float*)d_out;

    const int rows = in_sizes[0] / T;                       // 16384
    const int threads = 256;                                // 8 warps/block
    const int blocks = (rows * 32 + threads - 1) / threads; // 2048

    first_spike_fused<<<blocks, threads>>>(in, out, rows);
}